// round 1
// baseline (speedup 1.0000x reference)
#include <cuda_runtime.h>
#include <math.h>

#define BB 4
#define CC 8
#define HH 192
#define WW 256
#define HWP (HH*WW)
#define CHW (CC*HWP)
#define NBLK 48
#define GW 0.01f

__device__ float g_V0[BB*3*HWP];
__device__ float g_N0[BB*3*HWP];
__device__ float g_gx[BB*CC*HWP];
__device__ float g_gy[BB*CC*HWP];
__device__ float g_pose[BB*16];
__device__ double g_part[BB*NBLK*27];

// ---------------------------------------------------------------------------
// Precompute: copy pose, build V0, N0, dI0x, dI0y  (pose-independent)
// ---------------------------------------------------------------------------
__global__ void precompute_kernel(const float* __restrict__ pose,
                                  const float* __restrict__ I0,
                                  const float* __restrict__ depth0,
                                  const float* __restrict__ intr)
{
    int p = blockIdx.x * blockDim.x + threadIdx.x;
    if (p < BB*16) g_pose[p] = pose[p];
    if (p >= BB*HWP) return;
    int b = p / HWP;
    int i = p - b*HWP;
    int h = i / WW, w = i - h*WW;
    float fx = intr[b*4+0], fy = intr[b*4+1], cx = intr[b*4+2], cy = intr[b*4+3];
    int wl = max(w-1, 0), wr = min(w+1, WW-1);
    int hu = max(h-1, 0), hd = min(h+1, HH-1);
    const float* d0 = depth0 + b*HWP;
    float dc = d0[i];
    float dl = d0[h*WW+wl], dr = d0[h*WW+wr];
    float du_ = d0[hu*WW+w], dd = d0[hd*WW+w];
    float pxc = ((float)w - cx)/fx, pyc = ((float)h - cy)/fy;
    g_V0[b*3*HWP + 0*HWP + i] = pxc*dc;
    g_V0[b*3*HWP + 1*HWP + i] = pyc*dc;
    g_V0[b*3*HWP + 2*HWP + i] = dc;
    float pxl = ((float)wl - cx)/fx, pxr = ((float)wr - cx)/fx;
    float pyu = ((float)hu - cy)/fy, pyd = ((float)hd - cy)/fy;
    // central differences of V0 with edge clamping
    float dx0 = 0.5f*(pxr*dr - pxl*dl);
    float dx1 = 0.5f*(pyc*dr - pyc*dl);
    float dx2 = 0.5f*(dr - dl);
    float dy0 = 0.5f*(pxc*dd - pxc*du_);
    float dy1 = 0.5f*(pyd*dd - pyu*du_);
    float dy2 = 0.5f*(dd - du_);
    float nx = dx1*dy2 - dx2*dy1;
    float ny = dx2*dy0 - dx0*dy2;
    float nz = dx0*dy1 - dx1*dy0;
    float inv = 1.0f / sqrtf(nx*nx + ny*ny + nz*nz + 1e-12f);
    g_N0[b*3*HWP + 0*HWP + i] = nx*inv;
    g_N0[b*3*HWP + 1*HWP + i] = ny*inv;
    g_N0[b*3*HWP + 2*HWP + i] = nz*inv;
    #pragma unroll
    for (int c = 0; c < CC; c++) {
        const float* F = I0 + b*CHW + c*HWP;
        g_gx[b*CHW + c*HWP + i] = 0.5f*(F[h*WW+wr] - F[h*WW+wl]);
        g_gy[b*CHW + c*HWP + i] = 0.5f*(F[hd*WW+w] - F[hu*WW+w]);
    }
}

// ---------------------------------------------------------------------------
// Per-iteration reduction: build 21 (sym JtJ) + 6 (rhs) sums per batch
// ---------------------------------------------------------------------------
__global__ __launch_bounds__(256) void reduce_kernel(
    const float* __restrict__ I0, const float* __restrict__ I1,
    const float* __restrict__ depth0, const float* __restrict__ depth1,
    const float* __restrict__ intr)
{
    int b = blockIdx.y;
    float fx = intr[b*4+0], fy = intr[b*4+1], cx = intr[b*4+2], cy = intr[b*4+3];
    const float* P = g_pose + b*16;
    float R00=P[0], R01=P[1], R02=P[2],  t0=P[3];
    float R10=P[4], R11=P[5], R12=P[6],  t1=P[7];
    float R20=P[8], R21=P[9], R22=P[10], t2=P[11];

    float acc[27];
    #pragma unroll
    for (int k = 0; k < 27; k++) acc[k] = 0.f;

    for (int i = blockIdx.x*256 + threadIdx.x; i < HWP; i += NBLK*256) {
        float d1  = depth1[b*HWP + i];
        float d0c = depth0[b*HWP + i];
        if (!(d0c > 0.f && d1 > 0.f)) continue;
        int h = i / WW, w = i - h*WW;
        float px = ((float)w - cx)/fx, py = ((float)h - cy)/fy;
        float v1x = px*d1, v1y = py*d1, v1z = d1;
        float Xx = R00*v1x + R01*v1y + R02*v1z + t0;
        float Xy = R10*v1x + R11*v1y + R12*v1z + t1;
        float Xz = R20*v1x + R21*v1y + R22*v1z + t2;
        if (!(Xz > 1e-8f)) continue;
        float u = fx*Xx/Xz + cx;
        float v = fy*Xy/Xz + cy;
        if (!(u > 0.f && u < (float)(WW-1) && v > 0.f && v < (float)(HH-1))) continue;

        float u0f = floorf(u), v0f = floorf(v);
        float du = u - u0f, dv = v - v0f;
        int u0 = (int)u0f, v0 = (int)v0f;
        float w00 = (1.f-du)*(1.f-dv), w10 = du*(1.f-dv);
        float w01 = (1.f-du)*dv,       w11 = du*dv;
        int o00 = v0*WW + u0;

        // Jw = Jp @ [-skew(X) | I]
        float invz = 1.f / Xz;
        float a0 = fx*invz, a2 = -fx*Xx*invz*invz;
        float b1 = fy*invz, b2 = -fy*Xy*invz*invz;
        float Jw0[6] = { a2*Xy, a0*Xz - a2*Xx, -a0*Xy, a0, 0.f, a2 };
        float Jw1[6] = { b2*Xy - b1*Xz, -b2*Xx, b1*Xx, 0.f, b1, b2 };

        auto bilin = [&](const float* __restrict__ F) -> float {
            return w00*F[o00] + w10*F[o00+1] + w01*F[o00+WW] + w11*F[o00+WW+1];
        };
        auto addrow = [&](const float* J, float r) {
            float ar = fabsf(r);
            float wt = (ar <= 0.5f) ? 1.f : 0.5f / fmaxf(ar, 1e-12f);
            float wr = wt * r;
            int k = 0;
            #pragma unroll
            for (int ii = 0; ii < 6; ii++) {
                float wJ = wt * J[ii];
                #pragma unroll
                for (int jj = ii; jj < 6; jj++) acc[k++] += wJ * J[jj];
                acc[21+ii] += J[ii] * wr;
            }
        };

        // 8 photometric rows
        #pragma unroll
        for (int c = 0; c < CC; c++) {
            int cb = b*CHW + c*HWP;
            float I0w = bilin(I0 + cb);
            float gx  = bilin(g_gx + cb);
            float gy  = bilin(g_gy + cb);
            float r = I1[cb + i] - I0w;
            float J[6];
            #pragma unroll
            for (int k = 0; k < 6; k++) J[k] = gx*Jw0[k] + gy*Jw1[k];
            addrow(J, r);
        }

        // ICP point-to-plane row
        const float* V0b = g_V0 + b*3*HWP;
        const float* N0b = g_N0 + b*3*HWP;
        float rVx = bilin(V0b),         rVy = bilin(V0b + HWP), rVz = bilin(V0b + 2*HWP);
        float rNx = bilin(N0b),         rNy = bilin(N0b + HWP), rNz = bilin(N0b + 2*HWP);
        float dfx = Xx - rVx, dfy = Xy - rVy, dfz = Xz - rVz;
        float dn = sqrtf(dfx*dfx + dfy*dfy + dfz*dfz + 1e-12f);
        float q0 = rNx*R00 + rNy*R10 + rNz*R20;
        float q1 = rNx*R01 + rNy*R11 + rNz*R21;
        float q2 = rNx*R02 + rNy*R12 + rNz*R22;
        float Jr0 = q1*v1z - q2*v1y;
        float Jr1 = q2*v1x - q0*v1z;
        float Jr2 = q0*v1y - q1*v1x;
        float sd01 = (d1 / 525.0f) * 5.5f;
        float sd2  = d1*d1*0.4f / (525.0f*1.2f);
        float cov = (q0*q0 + q1*q1)*sd01*sd01 + q2*q2*sd2*sd2;
        float sigma = sqrtf(cov + 1e-8f);
        float sinv = 1.f / (sigma + 1e-8f);
        float res = (rNx*dfx + rNy*dfy + rNz*dfz) * sinv;
        if (dn > 0.1f) res = 1e-6f;
        float Jz[6] = { -Jr0*sinv*GW, -Jr1*sinv*GW, -Jr2*sinv*GW,
                         q0*sinv*GW,   q1*sinv*GW,   q2*sinv*GW };
        addrow(Jz, -GW * res);
    }

    // block reduction: fp32 warp shuffle tree, fp64 across warps
    __shared__ float sw[8][27];
    int lane = threadIdx.x & 31, wid = threadIdx.x >> 5;
    #pragma unroll
    for (int k = 0; k < 27; k++) {
        float val = acc[k];
        #pragma unroll
        for (int off = 16; off > 0; off >>= 1)
            val += __shfl_down_sync(0xffffffffu, val, off);
        if (lane == 0) sw[wid][k] = val;
    }
    __syncthreads();
    if (threadIdx.x < 27) {
        double s = 0.0;
        #pragma unroll
        for (int w2 = 0; w2 < 8; w2++) s += (double)sw[w2][threadIdx.x];
        g_part[(b*NBLK + blockIdx.x)*27 + threadIdx.x] = s;
    }
}

// ---------------------------------------------------------------------------
// Per-iteration solve: sum partials, solve 6x6, se3_exp, compose pose
// ---------------------------------------------------------------------------
__global__ void solve_kernel(float* __restrict__ out)
{
    int b = blockIdx.x;
    __shared__ double sv[27];
    int t = threadIdx.x;
    if (t < 27) {
        double s = 0.0;
        for (int k = 0; k < NBLK; k++) s += g_part[(b*NBLK + k)*27 + t];
        sv[t] = s;
    }
    __syncthreads();
    if (t != 0) return;

    double Hm[6][7];
    {
        int k = 0;
        for (int i = 0; i < 6; i++)
            for (int j = i; j < 6; j++) { Hm[i][j] = sv[k]; Hm[j][i] = sv[k]; k++; }
        for (int i = 0; i < 6; i++) Hm[i][i] += 1e-6;
        for (int i = 0; i < 6; i++) Hm[i][6] = sv[21 + i];
    }
    // Gaussian elimination with partial pivoting
    for (int col = 0; col < 6; col++) {
        int piv = col; double mx = fabs(Hm[col][col]);
        for (int r = col+1; r < 6; r++)
            if (fabs(Hm[r][col]) > mx) { mx = fabs(Hm[r][col]); piv = r; }
        if (piv != col)
            for (int c = col; c < 7; c++) { double tmp = Hm[col][c]; Hm[col][c] = Hm[piv][c]; Hm[piv][c] = tmp; }
        double inv = 1.0 / Hm[col][col];
        for (int r = col+1; r < 6; r++) {
            double f = Hm[r][col] * inv;
            for (int c = col; c < 7; c++) Hm[r][c] -= f * Hm[col][c];
        }
    }
    double xi[6];
    for (int r = 5; r >= 0; r--) {
        double s = Hm[r][6];
        for (int c = r+1; c < 6; c++) s -= Hm[r][c] * xi[c];
        xi[r] = s / Hm[r][r];
    }
    // se3 exp
    double wx = xi[0], wy = xi[1], wz = xi[2], vx = xi[3], vy = xi[4], vz = xi[5];
    double th2 = wx*wx + wy*wy + wz*wz;
    double A, Bc, Cc;
    if (th2 < 1e-8) { A = 1.0 - th2/6.0; Bc = 0.5 - th2/24.0; Cc = 1.0/6.0 - th2/120.0; }
    else {
        double th = sqrt(th2);
        A = sin(th)/th; Bc = (1.0 - cos(th))/th2; Cc = (th - sin(th))/(th2*th);
    }
    double K[3][3] = {{0,-wz,wy},{wz,0,-wx},{-wy,wx,0}};
    double K2[3][3];
    for (int i = 0; i < 3; i++)
        for (int j = 0; j < 3; j++)
            K2[i][j] = K[i][0]*K[0][j] + K[i][1]*K[1][j] + K[i][2]*K[2][j];
    double Re[3][3], Ve[3][3];
    for (int i = 0; i < 3; i++)
        for (int j = 0; j < 3; j++) {
            double id = (i == j) ? 1.0 : 0.0;
            Re[i][j] = id + A*K[i][j] + Bc*K2[i][j];
            Ve[i][j] = id + Bc*K[i][j] + Cc*K2[i][j];
        }
    double te[3];
    te[0] = Ve[0][0]*vx + Ve[0][1]*vy + Ve[0][2]*vz;
    te[1] = Ve[1][0]*vx + Ve[1][1]*vy + Ve[1][2]*vz;
    te[2] = Ve[2][0]*vx + Ve[2][1]*vy + Ve[2][2]*vz;

    float* Pp = g_pose + b*16;
    double Pd[4][4];
    for (int i = 0; i < 4; i++)
        for (int j = 0; j < 4; j++) Pd[i][j] = (double)Pp[i*4+j];
    double Nn[4][4];
    for (int j = 0; j < 4; j++) {
        for (int i = 0; i < 3; i++)
            Nn[i][j] = Re[i][0]*Pd[0][j] + Re[i][1]*Pd[1][j] + Re[i][2]*Pd[2][j] + te[i]*Pd[3][j];
        Nn[3][j] = Pd[3][j];
    }
    for (int i = 0; i < 4; i++)
        for (int j = 0; j < 4; j++) {
            float f = (float)Nn[i][j];
            Pp[i*4+j] = f;
            out[b*16 + i*4 + j] = f;
        }
}

// ---------------------------------------------------------------------------
extern "C" void kernel_launch(void* const* d_in, const int* in_sizes, int n_in,
                              void* d_out, int out_size)
{
    const float* pose   = (const float*)d_in[0];
    const float* I0     = (const float*)d_in[1];
    const float* I1     = (const float*)d_in[2];
    // d_in[3], d_in[4] = invD0, invD1 (unused by the forward pass)
    const float* intr   = (const float*)d_in[5];
    const float* depth0 = (const float*)d_in[6];
    const float* depth1 = (const float*)d_in[7];
    float* out = (float*)d_out;

    precompute_kernel<<<(BB*HWP + 255)/256, 256>>>(pose, I0, depth0, intr);
    for (int it = 0; it < 3; it++) {
        reduce_kernel<<<dim3(NBLK, BB), 256>>>(I0, I1, depth0, depth1, intr);
        solve_kernel<<<BB, 32>>>(out);
    }
}